// round 11
// baseline (speedup 1.0000x reference)
#include <cuda_runtime.h>
#include <cstdint>

// ---------------------------------------------------------------------------
// SpikingOpticalFlowBranch — fused flow-diff + conv3x3(2->64) + LIF scan.
// R11: R10 + software pipelining. R10 stalled every t on a long-scoreboard
// wait: conv reads frame t+1 loaded in the same iteration. Now frame t+2 is
// prefetched into registers at the top of iter t (LDG latency hidden under
// ~600 inst of conv/spike), STS'd at the bottom into a 3-buffer ring.
// Double-buffered chsum cuts barriers to 1 per t. Arithmetic order unchanged
// -> bit-identical numerics.
// Output layout: [0,160) readout, [160,3200) logits (t-major), [3200] sr.
// ---------------------------------------------------------------------------

#define T_STEPS 19
#define BATCH   16
#define HH      128
#define WW      128
#define NCH     64
#define QCH     16          // channels per CTA
#define OUTD    10
#define BETA_F  0.9f
#define THR_F   1.0f

#define TILE_R  32          // tile rows per CTA
#define TILE_C  16          // tile cols per CTA
#define HALO_R  34
#define HALO_C  18
#define FRAME_ELEMS (HALO_R*HALO_C*2)   // 1224 floats
#define LOAD_ITERS 5                     // ceil(1224/256)

__device__ int g_chsum[T_STEPS * BATCH * NCH];   // static-init 0; epilogue2 re-zeros

// ---------------------------------------------------------------------------
// Main kernel: grid = 16 batch x 32 tiles x 4 channel-quarters = 2048 blocks,
// 256 threads. Thread = 2 pixels (rows 2*typ, 2*typ+1) x 16 channels.
// ---------------------------------------------------------------------------
__global__ __launch_bounds__(256, 3)
void lif_main_kernel(const float* __restrict__ x,
                     const float* __restrict__ wconv,
                     const float* __restrict__ bconv) {
    __shared__ float  frame_s[3][FRAME_ELEMS];   // 3-deep ring of halo'd frames
    __shared__ float4 ws4[18 * 4];               // weights [tap][4 x float4] (16 ch)
    __shared__ float4 bs4[4];                    // bias (this quarter)
    __shared__ int    chsum_s[2][QCH];           // double-buffered counters

    const int tid  = threadIdx.x;
    const int lane = tid & 31;
    const int q    = blockIdx.x & 3;             // channel quarter
    const int tile = (blockIdx.x >> 2) & 31;     // 4 row-tiles x 8 col-tiles
    const int b    = blockIdx.x >> 7;            // batch
    const int th0  = (tile >> 3) * TILE_R;
    const int tw0  = (tile & 7) * TILE_C;
    const int tx   = tid & 15;                   // col in tile
    const int typ  = tid >> 4;                   // pixel-pair row (0..15)
    const int r0   = typ * 2;                    // first of the 2 rows

    // weights: global [ky][kx][ci][co] == [tap 0..17][co 0..63]; take our 16 co
    {
        float* wsf = reinterpret_cast<float*>(ws4);
        for (int i = tid; i < 18 * QCH; i += 256) {
            int tap = i >> 4, c = i & 15;
            wsf[i] = wconv[tap * NCH + q * QCH + c];
        }
        if (tid < QCH) {
            reinterpret_cast<float*>(bs4)[tid] = bconv[q * QCH + tid];
            chsum_s[0][tid] = 0;
            chsum_s[1][tid] = 0;
        }
    }

    // ---- hoisted loader state: indices are t-invariant ----
    int  gofs[LOAD_ITERS];
    bool gval[LOAD_ITERS];
#pragma unroll
    for (int k = 0; k < LOAD_ITERS; k++) {
        int i = tid + k * 256;
        gval[k] = false;
        gofs[k] = 0;
        if (i < FRAME_ELEMS) {
            int row = i / (HALO_C * 2);
            int rem = i - row * (HALO_C * 2);
            int col = rem >> 1;
            int c   = rem & 1;
            int gh  = th0 + row - 1;
            int gw  = tw0 + col - 1;
            if ((unsigned)gh < (unsigned)HH && (unsigned)gw < (unsigned)WW) {
                gval[k] = true;
                gofs[k] = (gh * WW + gw) * 2 + c;
            }
        }
    }

    auto load_frame_now = [&](int t, float* dst) {   // blocking (prologue only)
        const float* xt = x + ((size_t)t * BATCH + b) * (HH * WW * 2);
#pragma unroll
        for (int k = 0; k < LOAD_ITERS; k++) {
            int i = tid + k * 256;
            if (i < FRAME_ELEMS) dst[i] = gval[k] ? __ldg(xt + gofs[k]) : 0.0f;
        }
    };

    // prologue: frames 0,1 resident before the scan starts
    load_frame_now(0, frame_s[0]);
    load_frame_now(1, frame_s[1]);

    float V0[QCH], V1[QCH];
#pragma unroll
    for (int ch = 0; ch < QCH; ch++) { V0[ch] = 0.0f; V1[ch] = 0.0f; }

    int bi0 = 0, bi1 = 1, bi2 = 2;               // ring: t, t+1, t+2 buffers
    __syncthreads();

#pragma unroll 1
    for (int t = 0; t < T_STEPS; t++) {
        // ---- prefetch frame t+2 into registers (latency hidden by conv) ----
        float pre[LOAD_ITERS];
        if (t < T_STEPS - 1) {
            const float* xt = x + ((size_t)(t + 2) * BATCH + b) * (HH * WW * 2);
#pragma unroll
            for (int k = 0; k < LOAD_ITERS; k++)
                pre[k] = gval[k] ? __ldg(xt + gofs[k]) : 0.0f;
        }

        // ---- flush counters of step t-1 (other buffer than this step's) ----
        if (t > 0 && tid < QCH) {
            atomicAdd(&g_chsum[((t - 1) * BATCH + b) * NCH + q * QCH + tid],
                      chsum_s[(t - 1) & 1][tid]);
            chsum_s[(t - 1) & 1][tid] = 0;
        }

        const float2* n2 = reinterpret_cast<const float2*>(frame_s[bi1]);
        const float2* p2 = reinterpret_cast<const float2*>(frame_s[bi0]);

        // V = beta*V + bias  (per-channel order identical to R10)
#pragma unroll
        for (int j = 0; j < 4; j++) {
            float4 bb = bs4[j];
            V0[4*j+0] = BETA_F * V0[4*j+0] + bb.x;  V1[4*j+0] = BETA_F * V1[4*j+0] + bb.x;
            V0[4*j+1] = BETA_F * V0[4*j+1] + bb.y;  V1[4*j+1] = BETA_F * V1[4*j+1] + bb.y;
            V0[4*j+2] = BETA_F * V0[4*j+2] + bb.z;  V1[4*j+2] = BETA_F * V1[4*j+2] + bb.z;
            V0[4*j+3] = BETA_F * V0[4*j+3] + bb.w;  V1[4*j+3] = BETA_F * V1[4*j+3] + bb.w;
        }

        // conv: taps in ky,kx,ci ascending order (bit-identical to baseline)
#pragma unroll
        for (int ky = 0; ky < 3; ky++) {
            const int ra = (r0 + ky) * HALO_C + tx;       // pixel0 window row
            const int rb = ra + HALO_C;                    // pixel1 window row
            float2 a0, a1, a2, c0, c1, c2;
            a0.x = n2[ra+0].x - p2[ra+0].x;  a0.y = n2[ra+0].y - p2[ra+0].y;
            a1.x = n2[ra+1].x - p2[ra+1].x;  a1.y = n2[ra+1].y - p2[ra+1].y;
            a2.x = n2[ra+2].x - p2[ra+2].x;  a2.y = n2[ra+2].y - p2[ra+2].y;
            c0.x = n2[rb+0].x - p2[rb+0].x;  c0.y = n2[rb+0].y - p2[rb+0].y;
            c1.x = n2[rb+1].x - p2[rb+1].x;  c1.y = n2[rb+1].y - p2[rb+1].y;
            c2.x = n2[rb+2].x - p2[rb+2].x;  c2.y = n2[rb+2].y - p2[rb+2].y;
            const float2 A[3] = {a0, a1, a2};
            const float2 C[3] = {c0, c1, c2};
#pragma unroll
            for (int kx = 0; kx < 3; kx++) {
                const float fa0 = A[kx].x, fa1 = A[kx].y;   // pixel0, ci 0/1
                const float fc0 = C[kx].x, fc1 = C[kx].y;   // pixel1, ci 0/1
                const int tap0 = (ky * 3 + kx) * 2;
#pragma unroll
                for (int j = 0; j < 4; j++) {
                    float4 w = ws4[tap0 * 4 + j];
                    V0[4*j+0] += fa0 * w.x;  V1[4*j+0] += fc0 * w.x;
                    V0[4*j+1] += fa0 * w.y;  V1[4*j+1] += fc0 * w.y;
                    V0[4*j+2] += fa0 * w.z;  V1[4*j+2] += fc0 * w.z;
                    V0[4*j+3] += fa0 * w.w;  V1[4*j+3] += fc0 * w.w;
                }
#pragma unroll
                for (int j = 0; j < 4; j++) {
                    float4 w = ws4[(tap0 + 1) * 4 + j];
                    V0[4*j+0] += fa1 * w.x;  V1[4*j+0] += fc1 * w.x;
                    V0[4*j+1] += fa1 * w.y;  V1[4*j+1] += fc1 * w.y;
                    V0[4*j+2] += fa1 * w.z;  V1[4*j+2] += fc1 * w.z;
                    V0[4*j+3] += fa1 * w.w;  V1[4*j+3] += fc1 * w.w;
                }
            }
        }

        // spike + soft reset + warp-ballot counting (lane L<16 owns channel L)
        int acc = 0;
#pragma unroll
        for (int ch = 0; ch < QCH; ch++) {
            bool s0 = V0[ch] > THR_F;
            bool s1 = V1[ch] > THR_F;
            unsigned m0 = __ballot_sync(0xffffffffu, s0);
            unsigned m1 = __ballot_sync(0xffffffffu, s1);
            if (s0) V0[ch] -= THR_F;
            if (s1) V1[ch] -= THR_F;
            if (lane == ch) acc += __popc(m0) + __popc(m1);
        }
        if (lane < QCH) atomicAdd(&chsum_s[t & 1][lane], acc);

        // ---- commit prefetched frame t+2 to its ring slot ----
        if (t < T_STEPS - 1) {
            float* dst = frame_s[bi2];
#pragma unroll
            for (int k = 0; k < LOAD_ITERS; k++) {
                int i = tid + k * 256;
                if (i < FRAME_ELEMS) dst[i] = pre[k];
            }
        }

        // rotate ring
        int tmp = bi0; bi0 = bi1; bi1 = bi2; bi2 = tmp;

        // single barrier: orders (a) this t's chsum adds before next flush,
        // (b) STS of frame t+2 before next iteration's conv reads it,
        // (c) buffer bi2 reads (this t's p2) before overwrite next iteration.
        __syncthreads();
    }

    // final flush (t = 18 -> buffer 18&1 = 0)
    if (tid < QCH)
        atomicAdd(&g_chsum[((T_STEPS - 1) * BATCH + b) * NCH + q * QCH + tid],
                  chsum_s[0][tid]);
}

// ---------------------------------------------------------------------------
// Epilogue K1: grid 20. Blocks 0..18: logits for time t. Block 19: spike-rate.
// ---------------------------------------------------------------------------
__global__ void epilogue1_kernel(const float* __restrict__ w_head,
                                 const float* __restrict__ b_head,
                                 float* __restrict__ out) {
    const int t = blockIdx.x;
    const int tid = threadIdx.x;

    if (t < T_STEPS) {
        if (tid < BATCH * OUTD) {
            int b = tid / OUTD, o = tid % OUTD;
            const int* cs = g_chsum + (t * BATCH + b) * NCH;
            float acc = b_head[o];
            for (int ch = 0; ch < NCH; ch++)
                acc += ((float)cs[ch] * (1.0f / 16384.0f)) * w_head[ch * OUTD + o];
            out[160 + (t * BATCH + b) * OUTD + o] = acc;
        }
    } else {
        __shared__ long long part[256];
        long long tot = 0;
        for (int i = tid; i < T_STEPS * BATCH * NCH; i += 256)
            tot += (long long)g_chsum[i];
        part[tid] = tot;
        __syncthreads();
        for (int s = 128; s > 0; s >>= 1) {
            if (tid < s) part[tid] += part[tid + s];
            __syncthreads();
        }
        if (tid == 0)
            out[3200] = (float)((double)part[0] / 318767104.0);
    }
}

// ---------------------------------------------------------------------------
// Epilogue K2: readout = mean_t logits; re-zero g_chsum for next graph replay.
// ---------------------------------------------------------------------------
__global__ void epilogue2_kernel(float* __restrict__ out) {
    const int tid = threadIdx.x;
    if (tid < BATCH * OUTD) {
        int b = tid / OUTD, o = tid % OUTD;
        float s = 0.0f;
        for (int t = 0; t < T_STEPS; t++)
            s += out[160 + (t * BATCH + b) * OUTD + o];
        out[b * OUTD + o] = s * (1.0f / (float)T_STEPS);
    }
    for (int i = tid; i < T_STEPS * BATCH * NCH; i += 256) g_chsum[i] = 0;
}

// ---------------------------------------------------------------------------
extern "C" void kernel_launch(void* const* d_in, const int* in_sizes, int n_in,
                              void* d_out, int out_size) {
    const float* x     = (const float*)d_in[0];   // [20,16,128,128,2]
    const float* wconv = (const float*)d_in[1];   // [3,3,2,64]
    const float* bconv = (const float*)d_in[2];   // [64]
    const float* whead = (const float*)d_in[3];   // [64,10]
    const float* bhead = (const float*)d_in[4];   // [10]
    float* out = (float*)d_out;                   // 3201 floats

    lif_main_kernel<<<BATCH * 32 * 4, 256>>>(x, wconv, bconv);
    epilogue1_kernel<<<20, 256>>>(whead, bhead, out);
    epilogue2_kernel<<<1, 256>>>(out);
}

// round 15
// speedup vs baseline: 1.7739x; 1.7739x over previous
#include <cuda_runtime.h>
#include <cuda_bf16.h>
#include <cstdint>

// ---------------------------------------------------------------------------
// SpikingOpticalFlowBranch — tensor-core rewrite via mma.sync (R13).
// tcgen05 is rejected (harness PTX targets compute_103, not 103a), so the
// conv uses warp-level HMMA: mma.sync.m16n8k16.row.col.f32.bf16.bf16.f32.
// hi/lo split keeps fp32-like accuracy: u = a_hi*w_hi + a_hi*w_lo + a_lo*w_hi
// + bias (K=64: [hi18|hi18|lo18|1,1|0pad] x [w_hi|w_lo|w_hi|bh,bl|0]).
// V IS the accumulator fragment: per t, V *= beta, then the mma chain
// accumulates u+bias into it. CTA = 128 px x 64 ch; warp = 32 px (2 mtiles).
// Spike counts: fragment-aligned predicates -> shfl_xor tree -> smem atomics.
// Output layout: [0,160) readout, [160,3200) logits (t-major), [3200] sr.
// ---------------------------------------------------------------------------

#define T_STEPS 19
#define BATCH   16
#define HH      128
#define WW      128
#define NCH     64
#define OUTD    10
#define BETA_F  0.9f
#define THR_F   1.0f

#define TILE_R  8
#define TILE_C  16
#define HALO_R  10
#define HALO_C  18
#define FRAME_ELEMS (HALO_R*HALO_C*2)   // 360 floats
#define LOAD_ITERS 3

// smem byte offsets (A 1024-aligned for clean SW128 swizzle)
#define SM_A      0                     // 128 rows x 128B = 16384
#define SM_B      16384                 // 64 rows x 128B  = 8192
#define SM_FR0    24576                 // 3-frame ring, 1440B each
#define SM_FR1    26016
#define SM_FR2    27456
#define SM_CHSUM  28896                 // int[2][64]
#define SM_TOTAL  29408

#define SWZ(x) ((x) ^ (((x) >> 3) & 0x70))

__device__ int g_chsum[T_STEPS * BATCH * NCH];   // static-init 0; epilogue2 re-zeros

// ---- helpers --------------------------------------------------------------
__device__ __forceinline__ uint32_t smem_u32(const void* p) {
    uint32_t a;
    asm("{ .reg .u64 t; cvta.to.shared.u64 t, %1; cvt.u32.u64 %0, t; }"
        : "=r"(a) : "l"(p));
    return a;
}
__device__ __forceinline__ void ldmx4(uint32_t* r, uint32_t addr) {
    asm volatile("ldmatrix.sync.aligned.m8n8.x4.shared.b16 {%0,%1,%2,%3}, [%4];"
                 : "=r"(r[0]), "=r"(r[1]), "=r"(r[2]), "=r"(r[3]) : "r"(addr));
}
__device__ __forceinline__ void mma16816(float* c,
                                         const uint32_t* a,
                                         uint32_t b0, uint32_t b1) {
    asm volatile("mma.sync.aligned.m16n8k16.row.col.f32.bf16.bf16.f32 "
                 "{%0,%1,%2,%3}, {%4,%5,%6,%7}, {%8,%9}, {%0,%1,%2,%3};"
                 : "+f"(c[0]), "+f"(c[1]), "+f"(c[2]), "+f"(c[3])
                 : "r"(a[0]), "r"(a[1]), "r"(a[2]), "r"(a[3]), "r"(b0), "r"(b1));
}
__device__ __forceinline__ uint32_t pack_bf16x2(float lo, float hi) {
    uint32_t d;   // low 16 bits = lo (lower k col)
    asm("cvt.rn.satfinite.bf16x2.f32 %0, %1, %2;" : "=r"(d) : "f"(hi), "f"(lo));
    return d;
}

// ---------------------------------------------------------------------------
// Main kernel: grid = 16 batch x 128 tiles = 2048 CTAs, 128 threads.
// Warp w owns pixels [32w, 32w+32) as 2 mma m-tiles; V (64 ch) lives in the
// 2x8x4 fp32 accumulator fragments, carried across all 19 steps.
// ---------------------------------------------------------------------------
__global__ __launch_bounds__(128, 4)
void lif_mma_kernel(const float* __restrict__ x,
                    const float* __restrict__ wconv,
                    const float* __restrict__ bconv) {
    __shared__ __align__(1024) unsigned char smem[SM_TOTAL];
    const uint32_t sb = smem_u32(smem);

    const int tid  = threadIdx.x;
    const int lane = tid & 31;
    const int wrp  = tid >> 5;
    const int g    = lane >> 2;          // fragment group (row / col-n)
    const int tig  = lane & 3;           // thread-in-group
    const int b    = blockIdx.x >> 7;
    const int tile = blockIdx.x & 127;
    const int th0  = (tile >> 3) * TILE_R;
    const int tw0  = (tile & 7) * TILE_C;
    const int pr   = tid >> 4;           // this thread's pixel row in tile
    const int pc   = tid & 15;

    float* frame[3] = { reinterpret_cast<float*>(smem + SM_FR0),
                        reinterpret_cast<float*>(smem + SM_FR1),
                        reinterpret_cast<float*>(smem + SM_FR2) };
    int (*chs)[NCH] = reinterpret_cast<int (*)[NCH]>(smem + SM_CHSUM);

    // ---- zero B + A pad words 28-31 (cols 56-63) + chs ----
    for (int i = tid; i < 8192 / 4; i += 128)
        reinterpret_cast<uint32_t*>(smem + SM_B)[i] = 0;
    *reinterpret_cast<uint4*>(smem + SM_A + SWZ(tid * 128 + 112)) =
        make_uint4(0, 0, 0, 0);
    if (tid < NCH) { chs[0][tid] = 0; chs[1][tid] = 0; }

    // ---- build B once: row=ch, k cols [w_hi(18)|w_lo(18)|w_hi(18)|bh,bl|0] ----
    for (int i = tid; i < 18 * NCH; i += 128) {
        int tap = i >> 6, co = i & 63;
        float w = wconv[tap * NCH + co];
        __nv_bfloat16 hb = __float2bfloat16(w);
        __nv_bfloat16 lb = __float2bfloat16(w - __bfloat162float(hb));
        int rb = co * 128;
        *reinterpret_cast<__nv_bfloat16*>(smem + SM_B + SWZ(rb + tap * 2))        = hb;
        *reinterpret_cast<__nv_bfloat16*>(smem + SM_B + SWZ(rb + (18 + tap) * 2)) = lb;
        *reinterpret_cast<__nv_bfloat16*>(smem + SM_B + SWZ(rb + (36 + tap) * 2)) = hb;
    }
    if (tid < NCH) {
        float bv = bconv[tid];
        __nv_bfloat16 hb = __float2bfloat16(bv);
        __nv_bfloat16 lb = __float2bfloat16(bv - __bfloat162float(hb));
        int rb = tid * 128;
        *reinterpret_cast<__nv_bfloat16*>(smem + SM_B + SWZ(rb + 54 * 2)) = hb;
        *reinterpret_cast<__nv_bfloat16*>(smem + SM_B + SWZ(rb + 55 * 2)) = lb;
    }

    // ---- hoisted frame-loader offsets (t-invariant) ----
    int  gofs[LOAD_ITERS];
    bool gval[LOAD_ITERS];
#pragma unroll
    for (int k = 0; k < LOAD_ITERS; k++) {
        int i = tid + k * 128;
        gval[k] = false; gofs[k] = 0;
        if (i < FRAME_ELEMS) {
            int row = i / (HALO_C * 2);
            int rem = i - row * (HALO_C * 2);
            int col = rem >> 1;
            int c   = rem & 1;
            int gh  = th0 + row - 1;
            int gw  = tw0 + col - 1;
            if ((unsigned)gh < (unsigned)HH && (unsigned)gw < (unsigned)WW) {
                gval[k] = true; gofs[k] = (gh * WW + gw) * 2 + c;
            }
        }
    }
    auto load_frame = [&](int t, float* dst) {
        const float* xt = x + ((size_t)t * BATCH + b) * (HH * WW * 2);
#pragma unroll
        for (int k = 0; k < LOAD_ITERS; k++) {
            int i = tid + k * 128;
            if (i < FRAME_ELEMS) dst[i] = gval[k] ? __ldg(xt + gofs[k]) : 0.0f;
        }
    };

    load_frame(0, frame[0]);
    load_frame(1, frame[1]);

    // ---- per-thread operand addresses ----
    // A ldmatrix: warp rows 32w..+31; lane supplies row (lane&15), half (lane>>4)
    const int arow  = wrp * 32 + (lane & 15);
    const uint32_t abase = sb + SM_A + arow * 128;
    const uint32_t asw   = ((arow & 7) << 4);
    const uint32_t ahalf = (lane >> 4) * 16;
    // B scalar loads: row n*8+g, k pair at tig*2 (+8): swizzle xor = g<<4
    const uint32_t bbase = sb + SM_B + g * 128 + tig * 4;
    const uint32_t bsw   = (uint32_t)(g << 4);

    float V[64];                         // [m][n][frag] = V[(m*8+n)*4 + i]
#pragma unroll
    for (int i = 0; i < 64; i++) V[i] = 0.0f;

    __syncthreads();                     // B, frames 0/1, chs, A-pad ready

#pragma unroll 1
    for (int t = 0; t < T_STEPS; t++) {
        // stage frame t+2 (slot (t+2)%3 held tau=t-1, readers done pre-barrier)
        if (t < T_STEPS - 1) load_frame(t + 2, frame[(t + 2) % 3]);

        // flush spike counts of step t-1 (adds finished before this barrier)
        if (t > 0 && tid < NCH) {
            atomicAdd(&g_chsum[((t - 1) * BATCH + b) * NCH + tid],
                      chs[(t - 1) & 1][tid]);
            chs[(t - 1) & 1][tid] = 0;
        }

        // ---- build this pixel's A row: 18 flow taps -> hi/lo bf16, SW128 ----
        {
            const float2* n2 = reinterpret_cast<const float2*>(frame[(t + 1) % 3]);
            const float2* p2 = reinterpret_cast<const float2*>(frame[t % 3]);
            float a[18];
#pragma unroll
            for (int dy = 0; dy < 3; dy++)
#pragma unroll
                for (int dx = 0; dx < 3; dx++) {
                    int idx = (pr + dy) * HALO_C + (pc + dx);
                    float2 nn = n2[idx], pp = p2[idx];
                    a[(dy * 3 + dx) * 2 + 0] = nn.x - pp.x;
                    a[(dy * 3 + dx) * 2 + 1] = nn.y - pp.y;
                }
            uint32_t hw[9], lw[9];
#pragma unroll
            for (int j = 0; j < 9; j++) {
                uint32_t h = pack_bf16x2(a[2 * j], a[2 * j + 1]);
                float he = __uint_as_float(h << 16);
                float ho = __uint_as_float(h & 0xFFFF0000u);
                hw[j] = h;
                lw[j] = pack_bf16x2(a[2 * j] - he, a[2 * j + 1] - ho);
            }
            const int rb = tid * 128;   // words: 0-8 hi | 9-17 hi | 18-26 lo | 27=(1,1)
            *reinterpret_cast<uint4*>(smem + SM_A + SWZ(rb + 0))  =
                make_uint4(hw[0], hw[1], hw[2], hw[3]);
            *reinterpret_cast<uint4*>(smem + SM_A + SWZ(rb + 16)) =
                make_uint4(hw[4], hw[5], hw[6], hw[7]);
            *reinterpret_cast<uint4*>(smem + SM_A + SWZ(rb + 32)) =
                make_uint4(hw[8], hw[0], hw[1], hw[2]);
            *reinterpret_cast<uint4*>(smem + SM_A + SWZ(rb + 48)) =
                make_uint4(hw[3], hw[4], hw[5], hw[6]);
            *reinterpret_cast<uint4*>(smem + SM_A + SWZ(rb + 64)) =
                make_uint4(hw[7], hw[8], lw[0], lw[1]);
            *reinterpret_cast<uint4*>(smem + SM_A + SWZ(rb + 80)) =
                make_uint4(lw[2], lw[3], lw[4], lw[5]);
            *reinterpret_cast<uint4*>(smem + SM_A + SWZ(rb + 96)) =
                make_uint4(lw[6], lw[7], lw[8], 0x3F803F80u);
        }
        __syncwarp();                    // warp reads only its own 32 A rows

        // ---- LIF leak, then mma chain accumulates u + bias into V ----
#pragma unroll
        for (int i = 0; i < 64; i++) V[i] *= BETA_F;

#pragma unroll
        for (int k = 0; k < 4; k++) {
            uint32_t a0[4], a1[4];
            uint32_t adisp = (uint32_t)(k * 32 + ahalf) ^ asw;
            ldmx4(a0, abase + adisp);            // rows +0..15
            ldmx4(a1, abase + 2048 + adisp);     // rows +16..31 (swz unchanged)
#pragma unroll
            for (int n = 0; n < 8; n++) {
                uint32_t b0 = *reinterpret_cast<const uint32_t*>(
                    smem + (bbase - sb) + n * 1024 + ((uint32_t)(k * 32) ^ bsw));
                uint32_t b1 = *reinterpret_cast<const uint32_t*>(
                    smem + (bbase - sb) + n * 1024 + ((uint32_t)(k * 32 + 16) ^ bsw));
                mma16816(&V[(0 * 8 + n) * 4], a0, b0, b1);
                mma16816(&V[(1 * 8 + n) * 4], a1, b0, b1);
            }
        }

        // ---- spike + soft reset + fragment-aligned counting ----
#pragma unroll
        for (int n = 0; n < 8; n++) {
            int cA = 0, cB = 0;
#pragma unroll
            for (int m = 0; m < 2; m++) {
                float* v = &V[(m * 8 + n) * 4];
                if (v[0] > THR_F) { v[0] -= THR_F; cA++; }
                if (v[2] > THR_F) { v[2] -= THR_F; cA++; }
                if (v[1] > THR_F) { v[1] -= THR_F; cB++; }
                if (v[3] > THR_F) { v[3] -= THR_F; cB++; }
            }
            int val = cA | (cB << 16);
            val += __shfl_xor_sync(0xffffffffu, val, 4);
            val += __shfl_xor_sync(0xffffffffu, val, 8);
            val += __shfl_xor_sync(0xffffffffu, val, 16);
            if (lane < 4) {   // cols n*8 + lane*2, +1 (counts over this warp's 32 px)
                atomicAdd(&chs[t & 1][n * 8 + lane * 2 + 0], val & 0xffff);
                atomicAdd(&chs[t & 1][n * 8 + lane * 2 + 1], val >> 16);
            }
        }

        __syncthreads();   // orders: adds(t) before flush(t+1); frame STS before use
    }

    // final flush (t = 18 -> buffer 0)
    if (tid < NCH)
        atomicAdd(&g_chsum[((T_STEPS - 1) * BATCH + b) * NCH + tid],
                  chs[0][tid]);
}

// ---------------------------------------------------------------------------
// Epilogue K1: grid 20. Blocks 0..18: logits for time t. Block 19: spike-rate.
// ---------------------------------------------------------------------------
__global__ void epilogue1_kernel(const float* __restrict__ w_head,
                                 const float* __restrict__ b_head,
                                 float* __restrict__ out) {
    const int t = blockIdx.x;
    const int tid = threadIdx.x;

    if (t < T_STEPS) {
        if (tid < BATCH * OUTD) {
            int b = tid / OUTD, o = tid % OUTD;
            const int* cs = g_chsum + (t * BATCH + b) * NCH;
            float acc = b_head[o];
            for (int ch = 0; ch < NCH; ch++)
                acc += ((float)cs[ch] * (1.0f / 16384.0f)) * w_head[ch * OUTD + o];
            out[160 + (t * BATCH + b) * OUTD + o] = acc;
        }
    } else {
        __shared__ long long part[256];
        long long tot = 0;
        for (int i = tid; i < T_STEPS * BATCH * NCH; i += 256)
            tot += (long long)g_chsum[i];
        part[tid] = tot;
        __syncthreads();
        for (int s = 128; s > 0; s >>= 1) {
            if (tid < s) part[tid] += part[tid + s];
            __syncthreads();
        }
        if (tid == 0)
            out[3200] = (float)((double)part[0] / 318767104.0);
    }
}

// ---------------------------------------------------------------------------
// Epilogue K2: readout = mean_t logits; re-zero g_chsum for next graph replay.
// ---------------------------------------------------------------------------
__global__ void epilogue2_kernel(float* __restrict__ out) {
    const int tid = threadIdx.x;
    if (tid < BATCH * OUTD) {
        int b = tid / OUTD, o = tid % OUTD;
        float s = 0.0f;
        for (int t = 0; t < T_STEPS; t++)
            s += out[160 + (t * BATCH + b) * OUTD + o];
        out[b * OUTD + o] = s * (1.0f / (float)T_STEPS);
    }
    for (int i = tid; i < T_STEPS * BATCH * NCH; i += 256) g_chsum[i] = 0;
}

// ---------------------------------------------------------------------------
extern "C" void kernel_launch(void* const* d_in, const int* in_sizes, int n_in,
                              void* d_out, int out_size) {
    const float* x     = (const float*)d_in[0];   // [20,16,128,128,2]
    const float* wconv = (const float*)d_in[1];   // [3,3,2,64]
    const float* bconv = (const float*)d_in[2];   // [64]
    const float* whead = (const float*)d_in[3];   // [64,10]
    const float* bhead = (const float*)d_in[4];   // [10]
    float* out = (float*)d_out;                   // 3201 floats

    lif_mma_kernel<<<BATCH * 128, 128>>>(x, wconv, bconv);
    epilogue1_kernel<<<20, 256>>>(whead, bhead, out);
    epilogue2_kernel<<<1, 256>>>(out);
}

// round 16
// speedup vs baseline: 1.8870x; 1.0638x over previous
#include <cuda_runtime.h>
#include <cuda_bf16.h>
#include <cstdint>

// ---------------------------------------------------------------------------
// SpikingOpticalFlowBranch — HMMA mma.sync kernel, R16 tuning pass.
// vs R13: (1) B stored PRE-FRAGMENTED in mma register order -> per (n,k) one
// conflict-free LDS.64 at immediate offset (was 64 scalar LDS + addr ALU);
// (2) frame t+2 prefetched into registers at loop top, STS committed after
// the spike phase (hides LDG latency; R13 stalled at loop top);
// (3) spike counts for two n-tiles packed into one shfl-reduced word.
// Arithmetic identical to R13 -> rel_err unchanged (4.19e-4).
// Output layout: [0,160) readout, [160,3200) logits (t-major), [3200] sr.
// ---------------------------------------------------------------------------

#define T_STEPS 19
#define BATCH   16
#define HH      128
#define WW      128
#define NCH     64
#define OUTD    10
#define BETA_F  0.9f
#define THR_F   1.0f

#define TILE_R  8
#define TILE_C  16
#define HALO_R  10
#define HALO_C  18
#define FRAME_ELEMS (HALO_R*HALO_C*2)   // 360 floats
#define LOAD_ITERS 3

// smem byte offsets (A 1024-aligned for SW128 swizzle)
#define SM_A      0                     // 128 rows x 128B = 16384
#define SM_B      16384                 // fragmented B: 8 n x 4 k x 32 lanes x 8B = 8192
#define SM_FR0    24576                 // 3-frame ring, 1440B each
#define SM_FR1    26016
#define SM_FR2    27456
#define SM_CHSUM  28896                 // int[2][64]
#define SM_TOTAL  29408

#define SWZ(x) ((x) ^ (((x) >> 3) & 0x70))

__device__ int g_chsum[T_STEPS * BATCH * NCH];   // static-init 0; epilogue2 re-zeros

// ---- helpers --------------------------------------------------------------
__device__ __forceinline__ uint32_t smem_u32(const void* p) {
    uint32_t a;
    asm("{ .reg .u64 t; cvta.to.shared.u64 t, %1; cvt.u32.u64 %0, t; }"
        : "=r"(a) : "l"(p));
    return a;
}
__device__ __forceinline__ void ldmx4(uint32_t* r, uint32_t addr) {
    asm volatile("ldmatrix.sync.aligned.m8n8.x4.shared.b16 {%0,%1,%2,%3}, [%4];"
                 : "=r"(r[0]), "=r"(r[1]), "=r"(r[2]), "=r"(r[3]) : "r"(addr));
}
__device__ __forceinline__ void mma16816(float* c,
                                         const uint32_t* a,
                                         uint32_t b0, uint32_t b1) {
    asm volatile("mma.sync.aligned.m16n8k16.row.col.f32.bf16.bf16.f32 "
                 "{%0,%1,%2,%3}, {%4,%5,%6,%7}, {%8,%9}, {%0,%1,%2,%3};"
                 : "+f"(c[0]), "+f"(c[1]), "+f"(c[2]), "+f"(c[3])
                 : "r"(a[0]), "r"(a[1]), "r"(a[2]), "r"(a[3]), "r"(b0), "r"(b1));
}
__device__ __forceinline__ uint32_t pack_bf16x2(float lo, float hi) {
    uint32_t d;   // low 16 bits = lo
    asm("cvt.rn.satfinite.bf16x2.f32 %0, %1, %2;" : "=r"(d) : "f"(hi), "f"(lo));
    return d;
}
// bf16 hi/lo-split weight value for K-column k, channel ch
__device__ __forceinline__ float wsplit(const float* wconv, const float* bconv,
                                        int k, int ch) {
    if (k < 18) {
        float w = wconv[k * NCH + ch];
        return __bfloat162float(__float2bfloat16(w));
    }
    if (k < 36) {
        float w = wconv[(k - 18) * NCH + ch];
        return w - __bfloat162float(__float2bfloat16(w));
    }
    if (k < 54) {
        float w = wconv[(k - 36) * NCH + ch];
        return __bfloat162float(__float2bfloat16(w));
    }
    if (k == 54) {
        float bv = bconv[ch];
        return __bfloat162float(__float2bfloat16(bv));
    }
    if (k == 55) {
        float bv = bconv[ch];
        return bv - __bfloat162float(__float2bfloat16(bv));
    }
    return 0.0f;
}

// ---------------------------------------------------------------------------
// Main kernel: grid = 16 batch x 128 tiles = 2048 CTAs, 128 threads.
// Warp w owns pixels [32w, 32w+32) as 2 mma m-tiles; V (64 ch) lives in the
// 2x8x4 fp32 accumulator fragments, carried across all 19 steps.
// ---------------------------------------------------------------------------
__global__ __launch_bounds__(128, 4)
void lif_mma_kernel(const float* __restrict__ x,
                    const float* __restrict__ wconv,
                    const float* __restrict__ bconv) {
    __shared__ __align__(1024) unsigned char smem[SM_TOTAL];
    const uint32_t sb = smem_u32(smem);

    const int tid  = threadIdx.x;
    const int lane = tid & 31;
    const int wrp  = tid >> 5;
    const int b    = blockIdx.x >> 7;
    const int tile = blockIdx.x & 127;
    const int th0  = (tile >> 3) * TILE_R;
    const int tw0  = (tile & 7) * TILE_C;
    const int pr   = tid >> 4;           // this thread's pixel row in tile
    const int pc   = tid & 15;

    float* frame[3] = { reinterpret_cast<float*>(smem + SM_FR0),
                        reinterpret_cast<float*>(smem + SM_FR1),
                        reinterpret_cast<float*>(smem + SM_FR2) };
    int (*chs)[NCH] = reinterpret_cast<int (*)[NCH]>(smem + SM_CHSUM);

    // ---- zero A pad words 28-31 (K cols 56-63, never rewritten) + chs ----
    *reinterpret_cast<uint4*>(smem + SM_A + SWZ(tid * 128 + 112)) =
        make_uint4(0, 0, 0, 0);
    if (tid < NCH) { chs[0][tid] = 0; chs[1][tid] = 0; }

    // ---- build B pre-fragmented: region (n,kc) = 32 lanes x {b0,b1} ----
    // word i: n = i>>8-ish decode; value = bf16x2 of wsplit(k), wsplit(k+1)
    // for ch = n*8 + (lane>>2), k = kc*16 + half*8 + (lane&3)*2.
    for (int i = tid; i < 2048; i += 128) {
        int reg  = i >> 6;               // (n*4 + kc), 64 words per region
        int n    = reg >> 2;
        int kc   = reg & 3;
        int lw   = (i >> 1) & 31;
        int half = i & 1;
        int ch   = n * 8 + (lw >> 2);
        int k    = kc * 16 + half * 8 + (lw & 3) * 2;
        uint32_t v = pack_bf16x2(wsplit(wconv, bconv, k, ch),
                                 wsplit(wconv, bconv, k + 1, ch));
        reinterpret_cast<uint32_t*>(smem + SM_B)[i] = v;
    }

    // ---- hoisted frame-loader offsets (t-invariant) ----
    int  gofs[LOAD_ITERS];
    bool gval[LOAD_ITERS];
#pragma unroll
    for (int k = 0; k < LOAD_ITERS; k++) {
        int i = tid + k * 128;
        gval[k] = false; gofs[k] = 0;
        if (i < FRAME_ELEMS) {
            int row = i / (HALO_C * 2);
            int rem = i - row * (HALO_C * 2);
            int col = rem >> 1;
            int c   = rem & 1;
            int gh  = th0 + row - 1;
            int gw  = tw0 + col - 1;
            if ((unsigned)gh < (unsigned)HH && (unsigned)gw < (unsigned)WW) {
                gval[k] = true; gofs[k] = (gh * WW + gw) * 2 + c;
            }
        }
    }
    auto load_frame = [&](int t, float* dst) {
        const float* xt = x + ((size_t)t * BATCH + b) * (HH * WW * 2);
#pragma unroll
        for (int k = 0; k < LOAD_ITERS; k++) {
            int i = tid + k * 128;
            if (i < FRAME_ELEMS) dst[i] = gval[k] ? __ldg(xt + gofs[k]) : 0.0f;
        }
    };

    load_frame(0, frame[0]);
    load_frame(1, frame[1]);

    // ---- A ldmatrix addressing (identical to R13) ----
    const int arow  = wrp * 32 + (lane & 15);
    const uint32_t abase = sb + SM_A + arow * 128;
    const uint32_t asw   = ((arow & 7) << 4);
    const uint32_t ahalf = (lane >> 4) * 16;

    float V[64];                         // [m][n][frag] = V[(m*8+n)*4 + i]
#pragma unroll
    for (int i = 0; i < 64; i++) V[i] = 0.0f;

    __syncthreads();                     // B frags, frames 0/1, chs, A-pad ready

#pragma unroll 1
    for (int t = 0; t < T_STEPS; t++) {
        // prefetch frame t+2 into REGISTERS (STS deferred to after spike phase)
        float pre[LOAD_ITERS];
        if (t < T_STEPS - 1) {
            const float* xt = x + ((size_t)(t + 2) * BATCH + b) * (HH * WW * 2);
#pragma unroll
            for (int k = 0; k < LOAD_ITERS; k++)
                pre[k] = gval[k] ? __ldg(xt + gofs[k]) : 0.0f;
        }

        // flush spike counts of step t-1 (adds finished before last barrier)
        if (t > 0 && tid < NCH) {
            atomicAdd(&g_chsum[((t - 1) * BATCH + b) * NCH + tid],
                      chs[(t - 1) & 1][tid]);
            chs[(t - 1) & 1][tid] = 0;
        }

        // ---- build this pixel's A row: 18 flow taps -> hi/lo bf16, SW128 ----
        {
            const float2* n2 = reinterpret_cast<const float2*>(frame[(t + 1) % 3]);
            const float2* p2 = reinterpret_cast<const float2*>(frame[t % 3]);
            float a[18];
#pragma unroll
            for (int dy = 0; dy < 3; dy++)
#pragma unroll
                for (int dx = 0; dx < 3; dx++) {
                    int idx = (pr + dy) * HALO_C + (pc + dx);
                    float2 nn = n2[idx], pp = p2[idx];
                    a[(dy * 3 + dx) * 2 + 0] = nn.x - pp.x;
                    a[(dy * 3 + dx) * 2 + 1] = nn.y - pp.y;
                }
            uint32_t hw[9], lw[9];
#pragma unroll
            for (int j = 0; j < 9; j++) {
                uint32_t h = pack_bf16x2(a[2 * j], a[2 * j + 1]);
                float he = __uint_as_float(h << 16);
                float ho = __uint_as_float(h & 0xFFFF0000u);
                hw[j] = h;
                lw[j] = pack_bf16x2(a[2 * j] - he, a[2 * j + 1] - ho);
            }
            const int rb = tid * 128;   // words: 0-8 hi | 9-17 hi | 18-26 lo | 27=(1,1)
            *reinterpret_cast<uint4*>(smem + SM_A + SWZ(rb + 0))  =
                make_uint4(hw[0], hw[1], hw[2], hw[3]);
            *reinterpret_cast<uint4*>(smem + SM_A + SWZ(rb + 16)) =
                make_uint4(hw[4], hw[5], hw[6], hw[7]);
            *reinterpret_cast<uint4*>(smem + SM_A + SWZ(rb + 32)) =
                make_uint4(hw[8], hw[0], hw[1], hw[2]);
            *reinterpret_cast<uint4*>(smem + SM_A + SWZ(rb + 48)) =
                make_uint4(hw[3], hw[4], hw[5], hw[6]);
            *reinterpret_cast<uint4*>(smem + SM_A + SWZ(rb + 64)) =
                make_uint4(hw[7], hw[8], lw[0], lw[1]);
            *reinterpret_cast<uint4*>(smem + SM_A + SWZ(rb + 80)) =
                make_uint4(lw[2], lw[3], lw[4], lw[5]);
            *reinterpret_cast<uint4*>(smem + SM_A + SWZ(rb + 96)) =
                make_uint4(lw[6], lw[7], lw[8], 0x3F803F80u);
        }
        __syncwarp();                    // warp reads only its own 32 A rows

        // ---- LIF leak, then mma chain accumulates u + bias into V ----
#pragma unroll
        for (int i = 0; i < 64; i++) V[i] *= BETA_F;

#pragma unroll
        for (int k = 0; k < 4; k++) {
            uint32_t a0[4], a1[4];
            uint32_t adisp = (uint32_t)(k * 32 + ahalf) ^ asw;
            ldmx4(a0, abase + adisp);            // rows +0..15
            ldmx4(a1, abase + 2048 + adisp);     // rows +16..31
#pragma unroll
            for (int n = 0; n < 8; n++) {
                // pre-fragmented B: one conflict-free LDS.64, immediate offset
                uint2 bb = *reinterpret_cast<const uint2*>(
                    smem + SM_B + (n * 4 + k) * 256 + lane * 8);
                mma16816(&V[n * 4],       a0, bb.x, bb.y);
                mma16816(&V[(8 + n) * 4], a1, bb.x, bb.y);
            }
        }

        // ---- spike + soft reset + packed counting (2 n-tiles per shfl word) ----
#pragma unroll
        for (int np = 0; np < 4; np++) {
            const int n0 = np * 2, n1 = np * 2 + 1;
            int val;
            {
                int cA = 0, cB = 0;
#pragma unroll
                for (int m = 0; m < 2; m++) {
                    float* v = &V[(m * 8 + n0) * 4];
                    if (v[0] > THR_F) { v[0] -= THR_F; cA++; }
                    if (v[2] > THR_F) { v[2] -= THR_F; cA++; }
                    if (v[1] > THR_F) { v[1] -= THR_F; cB++; }
                    if (v[3] > THR_F) { v[3] -= THR_F; cB++; }
                }
                val = cA | (cB << 8);
            }
            {
                int cA = 0, cB = 0;
#pragma unroll
                for (int m = 0; m < 2; m++) {
                    float* v = &V[(m * 8 + n1) * 4];
                    if (v[0] > THR_F) { v[0] -= THR_F; cA++; }
                    if (v[2] > THR_F) { v[2] -= THR_F; cA++; }
                    if (v[1] > THR_F) { v[1] -= THR_F; cB++; }
                    if (v[3] > THR_F) { v[3] -= THR_F; cB++; }
                }
                val |= (cA << 16) | (cB << 24);
            }
            val += __shfl_xor_sync(0xffffffffu, val, 4);
            val += __shfl_xor_sync(0xffffffffu, val, 8);
            val += __shfl_xor_sync(0xffffffffu, val, 16);
            if (lane < 4) {              // lane = tig; byte counters max 32, no carry
                int* cc = chs[t & 1];
                atomicAdd(&cc[n0 * 8 + lane * 2 + 0], val & 0xff);
                atomicAdd(&cc[n0 * 8 + lane * 2 + 1], (val >> 8) & 0xff);
                atomicAdd(&cc[n1 * 8 + lane * 2 + 0], (val >> 16) & 0xff);
                atomicAdd(&cc[n1 * 8 + lane * 2 + 1], (val >> 24) & 0xff);
            }
        }

        // ---- commit prefetched frame t+2 (slot held t-1; readers done) ----
        if (t < T_STEPS - 1) {
            float* dst = frame[(t + 2) % 3];
#pragma unroll
            for (int k = 0; k < LOAD_ITERS; k++) {
                int i = tid + k * 128;
                if (i < FRAME_ELEMS) dst[i] = pre[k];
            }
        }

        __syncthreads();   // orders: adds(t) before flush(t+1); frame STS before use
    }

    // final flush (t = 18 -> buffer 0)
    if (tid < NCH)
        atomicAdd(&g_chsum[((T_STEPS - 1) * BATCH + b) * NCH + tid],
                  chs[0][tid]);
}

// ---------------------------------------------------------------------------
// Epilogue K1: grid 20. Blocks 0..18: logits for time t. Block 19: spike-rate.
// ---------------------------------------------------------------------------
__global__ void epilogue1_kernel(const float* __restrict__ w_head,
                                 const float* __restrict__ b_head,
                                 float* __restrict__ out) {
    const int t = blockIdx.x;
    const int tid = threadIdx.x;

    if (t < T_STEPS) {
        if (tid < BATCH * OUTD) {
            int b = tid / OUTD, o = tid % OUTD;
            const int* cs = g_chsum + (t * BATCH + b) * NCH;
            float acc = b_head[o];
            for (int ch = 0; ch < NCH; ch++)
                acc += ((float)cs[ch] * (1.0f / 16384.0f)) * w_head[ch * OUTD + o];
            out[160 + (t * BATCH + b) * OUTD + o] = acc;
        }
    } else {
        __shared__ long long part[256];
        long long tot = 0;
        for (int i = tid; i < T_STEPS * BATCH * NCH; i += 256)
            tot += (long long)g_chsum[i];
        part[tid] = tot;
        __syncthreads();
        for (int s = 128; s > 0; s >>= 1) {
            if (tid < s) part[tid] += part[tid + s];
            __syncthreads();
        }
        if (tid == 0)
            out[3200] = (float)((double)part[0] / 318767104.0);
    }
}

// ---------------------------------------------------------------------------
// Epilogue K2: readout = mean_t logits; re-zero g_chsum for next graph replay.
// ---------------------------------------------------------------------------
__global__ void epilogue2_kernel(float* __restrict__ out) {
    const int tid = threadIdx.x;
    if (tid < BATCH * OUTD) {
        int b = tid / OUTD, o = tid % OUTD;
        float s = 0.0f;
        for (int t = 0; t < T_STEPS; t++)
            s += out[160 + (t * BATCH + b) * OUTD + o];
        out[b * OUTD + o] = s * (1.0f / (float)T_STEPS);
    }
    for (int i = tid; i < T_STEPS * BATCH * NCH; i += 256) g_chsum[i] = 0;
}

// ---------------------------------------------------------------------------
extern "C" void kernel_launch(void* const* d_in, const int* in_sizes, int n_in,
                              void* d_out, int out_size) {
    const float* x     = (const float*)d_in[0];   // [20,16,128,128,2]
    const float* wconv = (const float*)d_in[1];   // [3,3,2,64]
    const float* bconv = (const float*)d_in[2];   // [64]
    const float* whead = (const float*)d_in[3];   // [64,10]
    const float* bhead = (const float*)d_in[4];   // [10]
    float* out = (float*)d_out;                   // 3201 floats

    lif_mma_kernel<<<BATCH * 128, 128>>>(x, wconv, bconv);
    epilogue1_kernel<<<20, 256>>>(whead, bhead, out);
    epilogue2_kernel<<<1, 256>>>(out);
}

// round 17
// speedup vs baseline: 1.9267x; 1.0210x over previous
#include <cuda_runtime.h>
#include <cuda_bf16.h>
#include <cstdint>

// ---------------------------------------------------------------------------
// SpikingOpticalFlowBranch — HMMA mma.sync kernel, R17 tuning pass.
// vs R16: flow hi/lo bf16 split factored OUT of the per-tap gather. A new
// per-t flow pass computes (hi,lo) bf16x2 ONCE per halo element (was 9x,
// once per consuming pixel); A-build becomes 9 LDS.64 + 7 STS.128 at
// t-invariant precomputed swizzled addresses. Same split arithmetic ->
// rel_err unchanged (8.29e-5). Costs +1 barrier/t.
// Output layout: [0,160) readout, [160,3200) logits (t-major), [3200] sr.
// ---------------------------------------------------------------------------

#define T_STEPS 19
#define BATCH   16
#define HH      128
#define WW      128
#define NCH     64
#define OUTD    10
#define BETA_F  0.9f
#define THR_F   1.0f

#define TILE_R  8
#define TILE_C  16
#define HALO_R  10
#define HALO_C  18
#define HALO_POS (HALO_R*HALO_C)        // 180 positions (2 ch packed per pos)
#define FRAME_ELEMS (HALO_POS*2)        // 360 floats
#define LOAD_ITERS 3

// smem byte offsets (A 1024-aligned for SW128 swizzle)
#define SM_A      0                     // 128 rows x 128B = 16384
#define SM_B      16384                 // fragmented B: 8n x 4k x 32 lanes x 8B
#define SM_FR0    24576                 // 3-frame ring, 1440B each
#define SM_FR1    26016
#define SM_FR2    27456
#define SM_FLOW   28896                 // uint2[180]: (hi bf16x2, lo bf16x2)
#define SM_CHSUM  30336                 // int[2][64]
#define SM_TOTAL  30848

#define SWZ(x) ((x) ^ (((x) >> 3) & 0x70))

__device__ int g_chsum[T_STEPS * BATCH * NCH];   // static-init 0; epilogue2 re-zeros

// ---- helpers --------------------------------------------------------------
__device__ __forceinline__ uint32_t smem_u32(const void* p) {
    uint32_t a;
    asm("{ .reg .u64 t; cvta.to.shared.u64 t, %1; cvt.u32.u64 %0, t; }"
        : "=r"(a) : "l"(p));
    return a;
}
__device__ __forceinline__ void ldmx4(uint32_t* r, uint32_t addr) {
    asm volatile("ldmatrix.sync.aligned.m8n8.x4.shared.b16 {%0,%1,%2,%3}, [%4];"
                 : "=r"(r[0]), "=r"(r[1]), "=r"(r[2]), "=r"(r[3]) : "r"(addr));
}
__device__ __forceinline__ void mma16816(float* c,
                                         const uint32_t* a,
                                         uint32_t b0, uint32_t b1) {
    asm volatile("mma.sync.aligned.m16n8k16.row.col.f32.bf16.bf16.f32 "
                 "{%0,%1,%2,%3}, {%4,%5,%6,%7}, {%8,%9}, {%0,%1,%2,%3};"
                 : "+f"(c[0]), "+f"(c[1]), "+f"(c[2]), "+f"(c[3])
                 : "r"(a[0]), "r"(a[1]), "r"(a[2]), "r"(a[3]), "r"(b0), "r"(b1));
}
__device__ __forceinline__ uint32_t pack_bf16x2(float lo, float hi) {
    uint32_t d;   // low 16 bits = lo
    asm("cvt.rn.satfinite.bf16x2.f32 %0, %1, %2;" : "=r"(d) : "f"(hi), "f"(lo));
    return d;
}
// bf16 hi/lo-split weight value for K-column k, channel ch (R16 layout)
__device__ __forceinline__ float wsplit(const float* wconv, const float* bconv,
                                        int k, int ch) {
    if (k < 18) {
        float w = wconv[k * NCH + ch];
        return __bfloat162float(__float2bfloat16(w));
    }
    if (k < 36) {
        float w = wconv[(k - 18) * NCH + ch];
        return w - __bfloat162float(__float2bfloat16(w));
    }
    if (k < 54) {
        float w = wconv[(k - 36) * NCH + ch];
        return __bfloat162float(__float2bfloat16(w));
    }
    if (k == 54) {
        float bv = bconv[ch];
        return __bfloat162float(__float2bfloat16(bv));
    }
    if (k == 55) {
        float bv = bconv[ch];
        return bv - __bfloat162float(__float2bfloat16(bv));
    }
    return 0.0f;
}

// ---------------------------------------------------------------------------
// Main kernel: grid = 16 batch x 128 tiles = 2048 CTAs, 128 threads.
// Warp w owns pixels [32w, 32w+32) as 2 mma m-tiles; V (64 ch) lives in the
// 2x8x4 fp32 accumulator fragments, carried across all 19 steps.
// A row K layout: [a_hi(18) | a_hi(18) | a_lo(18) | 1,1 | 0pad(8)].
// ---------------------------------------------------------------------------
__global__ __launch_bounds__(128, 4)
void lif_mma_kernel(const float* __restrict__ x,
                    const float* __restrict__ wconv,
                    const float* __restrict__ bconv) {
    __shared__ __align__(1024) unsigned char smem[SM_TOTAL];
    const uint32_t sb = smem_u32(smem);

    const int tid  = threadIdx.x;
    const int lane = tid & 31;
    const int wrp  = tid >> 5;
    const int b    = blockIdx.x >> 7;
    const int tile = blockIdx.x & 127;
    const int th0  = (tile >> 3) * TILE_R;
    const int tw0  = (tile & 7) * TILE_C;
    const int pr   = tid >> 4;           // this thread's pixel row in tile
    const int pc   = tid & 15;

    float* frame[3] = { reinterpret_cast<float*>(smem + SM_FR0),
                        reinterpret_cast<float*>(smem + SM_FR1),
                        reinterpret_cast<float*>(smem + SM_FR2) };
    uint2* flow = reinterpret_cast<uint2*>(smem + SM_FLOW);
    int (*chs)[NCH] = reinterpret_cast<int (*)[NCH]>(smem + SM_CHSUM);

    // ---- zero A pad words 28-31 (K cols 56-63, never rewritten) + chs ----
    *reinterpret_cast<uint4*>(smem + SM_A + SWZ(tid * 128 + 112)) =
        make_uint4(0, 0, 0, 0);
    if (tid < NCH) { chs[0][tid] = 0; chs[1][tid] = 0; }

    // ---- build B pre-fragmented (identical to R16) ----
    for (int i = tid; i < 2048; i += 128) {
        int reg  = i >> 6;
        int n    = reg >> 2;
        int kc   = reg & 3;
        int lw   = (i >> 1) & 31;
        int half = i & 1;
        int ch   = n * 8 + (lw >> 2);
        int k    = kc * 16 + half * 8 + (lw & 3) * 2;
        uint32_t v = pack_bf16x2(wsplit(wconv, bconv, k, ch),
                                 wsplit(wconv, bconv, k + 1, ch));
        reinterpret_cast<uint32_t*>(smem + SM_B)[i] = v;
    }

    // ---- hoisted frame-loader offsets (t-invariant) ----
    int  gofs[LOAD_ITERS];
    bool gval[LOAD_ITERS];
#pragma unroll
    for (int k = 0; k < LOAD_ITERS; k++) {
        int i = tid + k * 128;
        gval[k] = false; gofs[k] = 0;
        if (i < FRAME_ELEMS) {
            int row = i / (HALO_C * 2);
            int rem = i - row * (HALO_C * 2);
            int col = rem >> 1;
            int c   = rem & 1;
            int gh  = th0 + row - 1;
            int gw  = tw0 + col - 1;
            if ((unsigned)gh < (unsigned)HH && (unsigned)gw < (unsigned)WW) {
                gval[k] = true; gofs[k] = (gh * WW + gw) * 2 + c;
            }
        }
    }
    auto load_frame = [&](int t, float* dst) {
        const float* xt = x + ((size_t)t * BATCH + b) * (HH * WW * 2);
#pragma unroll
        for (int k = 0; k < LOAD_ITERS; k++) {
            int i = tid + k * 128;
            if (i < FRAME_ELEMS) dst[i] = gval[k] ? __ldg(xt + gofs[k]) : 0.0f;
        }
    };

    load_frame(0, frame[0]);
    load_frame(1, frame[1]);

    // ---- precomputed addresses (t-invariant) ----
    // A STS: 7 swizzled uint4 slots of this thread's row
    uint4* asts[7];
#pragma unroll
    for (int i = 0; i < 7; i++)
        asts[i] = reinterpret_cast<uint4*>(smem + SM_A + SWZ(tid * 128 + 16 * i));
    // tap gather base: flow + (pr*18 + pc); offsets dy*18+dx are immediates
    const uint2* fbase = flow + pr * HALO_C + pc;
    // A ldmatrix addressing (identical to R13/R16)
    const int arow  = wrp * 32 + (lane & 15);
    const uint32_t abase = sb + SM_A + arow * 128;
    const uint32_t asw   = ((arow & 7) << 4);
    const uint32_t ahalf = (lane >> 4) * 16;

    float V[64];                         // [m][n][frag] = V[(m*8+n)*4 + i]
#pragma unroll
    for (int i = 0; i < 64; i++) V[i] = 0.0f;

    __syncthreads();                     // B frags, frames 0/1, chs, A-pad ready

#pragma unroll 1
    for (int t = 0; t < T_STEPS; t++) {
        // prefetch frame t+2 into REGISTERS (STS deferred to after spike phase)
        float pre[LOAD_ITERS];
        if (t < T_STEPS - 1) {
            const float* xt = x + ((size_t)(t + 2) * BATCH + b) * (HH * WW * 2);
#pragma unroll
            for (int k = 0; k < LOAD_ITERS; k++)
                pre[k] = gval[k] ? __ldg(xt + gofs[k]) : 0.0f;
        }

        // flush spike counts of step t-1 (adds finished before last barrier)
        if (t > 0 && tid < NCH) {
            atomicAdd(&g_chsum[((t - 1) * BATCH + b) * NCH + tid],
                      chs[(t - 1) & 1][tid]);
            chs[(t - 1) & 1][tid] = 0;
        }

        // ---- flow pass: hi/lo bf16 split ONCE per halo element ----
        {
            const float2* nf = reinterpret_cast<const float2*>(frame[(t + 1) % 3]);
            const float2* pf = reinterpret_cast<const float2*>(frame[t % 3]);
#pragma unroll
            for (int it = 0; it < 2; it++) {
                int p = tid + it * 128;
                if (p < HALO_POS) {
                    float2 nn = nf[p], pp = pf[p];
                    float d0 = nn.x - pp.x;
                    float d1 = nn.y - pp.y;
                    uint32_t h = pack_bf16x2(d0, d1);
                    float he = __uint_as_float(h << 16);
                    float ho = __uint_as_float(h & 0xFFFF0000u);
                    uint32_t l = pack_bf16x2(d0 - he, d1 - ho);
                    flow[p] = make_uint2(h, l);
                }
            }
        }
        __syncthreads();                 // flow ready (taps cross warp regions)

        // ---- A build: 9 LDS.64 gathers + 7 STS.128 at hoisted addresses ----
        {
            uint2 f0 = fbase[0 * HALO_C + 0];
            uint2 f1 = fbase[0 * HALO_C + 1];
            uint2 f2 = fbase[0 * HALO_C + 2];
            uint2 f3 = fbase[1 * HALO_C + 0];
            uint2 f4 = fbase[1 * HALO_C + 1];
            uint2 f5 = fbase[1 * HALO_C + 2];
            uint2 f6 = fbase[2 * HALO_C + 0];
            uint2 f7 = fbase[2 * HALO_C + 1];
            uint2 f8 = fbase[2 * HALO_C + 2];
            *asts[0] = make_uint4(f0.x, f1.x, f2.x, f3.x);
            *asts[1] = make_uint4(f4.x, f5.x, f6.x, f7.x);
            *asts[2] = make_uint4(f8.x, f0.x, f1.x, f2.x);
            *asts[3] = make_uint4(f3.x, f4.x, f5.x, f6.x);
            *asts[4] = make_uint4(f7.x, f8.x, f0.y, f1.y);
            *asts[5] = make_uint4(f2.y, f3.y, f4.y, f5.y);
            *asts[6] = make_uint4(f6.y, f7.y, f8.y, 0x3F803F80u);
        }
        __syncwarp();                    // warp reads only its own 32 A rows

        // ---- LIF leak, then mma chain accumulates u + bias into V ----
#pragma unroll
        for (int i = 0; i < 64; i++) V[i] *= BETA_F;

#pragma unroll
        for (int k = 0; k < 4; k++) {
            uint32_t a0[4], a1[4];
            uint32_t adisp = (uint32_t)(k * 32 + ahalf) ^ asw;
            ldmx4(a0, abase + adisp);            // rows +0..15
            ldmx4(a1, abase + 2048 + adisp);     // rows +16..31
#pragma unroll
            for (int n = 0; n < 8; n++) {
                uint2 bb = *reinterpret_cast<const uint2*>(
                    smem + SM_B + (n * 4 + k) * 256 + lane * 8);
                mma16816(&V[n * 4],       a0, bb.x, bb.y);
                mma16816(&V[(8 + n) * 4], a1, bb.x, bb.y);
            }
        }

        // ---- spike + soft reset + packed counting (2 n-tiles per word) ----
#pragma unroll
        for (int np = 0; np < 4; np++) {
            const int n0 = np * 2, n1 = np * 2 + 1;
            int val;
            {
                int cA = 0, cB = 0;
#pragma unroll
                for (int m = 0; m < 2; m++) {
                    float* v = &V[(m * 8 + n0) * 4];
                    if (v[0] > THR_F) { v[0] -= THR_F; cA++; }
                    if (v[2] > THR_F) { v[2] -= THR_F; cA++; }
                    if (v[1] > THR_F) { v[1] -= THR_F; cB++; }
                    if (v[3] > THR_F) { v[3] -= THR_F; cB++; }
                }
                val = cA | (cB << 8);
            }
            {
                int cA = 0, cB = 0;
#pragma unroll
                for (int m = 0; m < 2; m++) {
                    float* v = &V[(m * 8 + n1) * 4];
                    if (v[0] > THR_F) { v[0] -= THR_F; cA++; }
                    if (v[2] > THR_F) { v[2] -= THR_F; cA++; }
                    if (v[1] > THR_F) { v[1] -= THR_F; cB++; }
                    if (v[3] > THR_F) { v[3] -= THR_F; cB++; }
                }
                val |= (cA << 16) | (cB << 24);
            }
            val += __shfl_xor_sync(0xffffffffu, val, 4);
            val += __shfl_xor_sync(0xffffffffu, val, 8);
            val += __shfl_xor_sync(0xffffffffu, val, 16);
            if (lane < 4) {              // byte counters max 32, no carry
                int* cc = chs[t & 1];
                atomicAdd(&cc[n0 * 8 + lane * 2 + 0], val & 0xff);
                atomicAdd(&cc[n0 * 8 + lane * 2 + 1], (val >> 8) & 0xff);
                atomicAdd(&cc[n1 * 8 + lane * 2 + 0], (val >> 16) & 0xff);
                atomicAdd(&cc[n1 * 8 + lane * 2 + 1], (val >> 24) & 0xff);
            }
        }

        // ---- commit prefetched frame t+2 (slot held t-1; readers done) ----
        if (t < T_STEPS - 1) {
            float* dst = frame[(t + 2) % 3];
#pragma unroll
            for (int k = 0; k < LOAD_ITERS; k++) {
                int i = tid + k * 128;
                if (i < FRAME_ELEMS) dst[i] = pre[k];
            }
        }

        __syncthreads();   // orders: adds(t) pre-flush(t+1); frame/flow reuse
    }

    // final flush (t = 18 -> buffer 0)
    if (tid < NCH)
        atomicAdd(&g_chsum[((T_STEPS - 1) * BATCH + b) * NCH + tid],
                  chs[0][tid]);
}

// ---------------------------------------------------------------------------
// Epilogue K1: grid 20. Blocks 0..18: logits for time t. Block 19: spike-rate.
// ---------------------------------------------------------------------------
__global__ void epilogue1_kernel(const float* __restrict__ w_head,
                                 const float* __restrict__ b_head,
                                 float* __restrict__ out) {
    const int t = blockIdx.x;
    const int tid = threadIdx.x;

    if (t < T_STEPS) {
        if (tid < BATCH * OUTD) {
            int b = tid / OUTD, o = tid % OUTD;
            const int* cs = g_chsum + (t * BATCH + b) * NCH;
            float acc = b_head[o];
            for (int ch = 0; ch < NCH; ch++)
                acc += ((float)cs[ch] * (1.0f / 16384.0f)) * w_head[ch * OUTD + o];
            out[160 + (t * BATCH + b) * OUTD + o] = acc;
        }
    } else {
        __shared__ long long part[256];
        long long tot = 0;
        for (int i = tid; i < T_STEPS * BATCH * NCH; i += 256)
            tot += (long long)g_chsum[i];
        part[tid] = tot;
        __syncthreads();
        for (int s = 128; s > 0; s >>= 1) {
            if (tid < s) part[tid] += part[tid + s];
            __syncthreads();
        }
        if (tid == 0)
            out[3200] = (float)((double)part[0] / 318767104.0);
    }
}

// ---------------------------------------------------------------------------
// Epilogue K2: readout = mean_t logits; re-zero g_chsum for next graph replay.
// ---------------------------------------------------------------------------
__global__ void epilogue2_kernel(float* __restrict__ out) {
    const int tid = threadIdx.x;
    if (tid < BATCH * OUTD) {
        int b = tid / OUTD, o = tid % OUTD;
        float s = 0.0f;
        for (int t = 0; t < T_STEPS; t++)
            s += out[160 + (t * BATCH + b) * OUTD + o];
        out[b * OUTD + o] = s * (1.0f / (float)T_STEPS);
    }
    for (int i = tid; i < T_STEPS * BATCH * NCH; i += 256) g_chsum[i] = 0;
}

// ---------------------------------------------------------------------------
extern "C" void kernel_launch(void* const* d_in, const int* in_sizes, int n_in,
                              void* d_out, int out_size) {
    const float* x     = (const float*)d_in[0];   // [20,16,128,128,2]
    const float* wconv = (const float*)d_in[1];   // [3,3,2,64]
    const float* bconv = (const float*)d_in[2];   // [64]
    const float* whead = (const float*)d_in[3];   // [64,10]
    const float* bhead = (const float*)d_in[4];   // [10]
    float* out = (float*)d_out;                   // 3201 floats

    lif_mma_kernel<<<BATCH * 128, 128>>>(x, wconv, bconv);
    epilogue1_kernel<<<20, 256>>>(whead, bhead, out);
    epilogue2_kernel<<<1, 256>>>(out);
}